// round 2
// baseline (speedup 1.0000x reference)
#include <cuda_runtime.h>
#include <cstdint>
#include <cstddef>

// ---------------------------------------------------------------------------
// Problem constants
// ---------------------------------------------------------------------------
#define BATCH   256
#define SEQ     512
#define NIN     256
#define HID     256
#define G3      768          // 3*HID
#define LAYERS  2
#define ROWS    (BATCH*SEQ)  // 131072
#define RANKSUM 96           // 64 + 32

// ---------------------------------------------------------------------------
// Static device scratch (no cudaMalloc allowed)
// ---------------------------------------------------------------------------
__device__ float g_t_buf[(size_t)ROWS * RANKSUM];   //  50 MB  stage-1 of wx
__device__ float g_wx_buf[(size_t)ROWS * G3];       // 403 MB  wx (all t)
__device__ float g_x1[(size_t)ROWS * HID];          // 134 MB  layer-0 output
__device__ float g_P [LAYERS * NIN * RANKSUM];      // [Wd|Wo]
__device__ float g_Q [LAYERS * RANKSUM * G3];       // [Wdg;Wog]
__device__ float g_Pu[LAYERS * HID * RANKSUM];      // [Ud|Uo]
__device__ float g_Qu[LAYERS * RANKSUM * G3];       // [Udg;Uog]
__device__ float g_Ueff[LAYERS * HID * G3];         // dense recurrent weight
__device__ float g_h [2 * 16 * HID * 16];           // h double buffer [buf][grp][k][b]

// ---------------------------------------------------------------------------
// f32x2 packed-math helpers (sm_103a; FFMA2 only reachable via PTX)
// ---------------------------------------------------------------------------
__device__ __forceinline__ unsigned long long dup2(float a)
{
    unsigned long long r;
    asm("mov.b64 %0, {%1, %1};" : "=l"(r) : "f"(a));
    return r;
}
__device__ __forceinline__ void fma2(unsigned long long& acc,
                                     unsigned long long a, unsigned long long b)
{
    asm("fma.rn.f32x2 %0, %1, %2, %0;" : "+l"(acc) : "l"(a), "l"(b));
}
__device__ __forceinline__ unsigned long long add2(unsigned long long a,
                                                   unsigned long long b)
{
    unsigned long long r;
    asm("add.rn.f32x2 %0, %1, %2;" : "=l"(r) : "l"(a), "l"(b));
    return r;
}
__device__ __forceinline__ float2 unpack2(unsigned long long v)
{
    float2 f;
    asm("mov.b64 {%0, %1}, %2;" : "=f"(f.x), "=f"(f.y) : "l"(v));
    return f;
}

// ---------------------------------------------------------------------------
// Pack kernel: concatenate low-rank factors
// ---------------------------------------------------------------------------
__global__ void pack_kernel(const float* __restrict__ Wd, const float* __restrict__ Wdg,
                            const float* __restrict__ Wo, const float* __restrict__ Wog,
                            const float* __restrict__ Ud, const float* __restrict__ Udg,
                            const float* __restrict__ Uo, const float* __restrict__ Uog)
{
    int idx = blockIdx.x * 256 + threadIdx.x;
    const int QN = LAYERS * RANKSUM * G3;   // 147456
    const int PN = LAYERS * NIN * RANKSUM;  // 49152
    if (idx < QN) {
        int l = idx / (RANKSUM * G3);
        int rem = idx - l * (RANKSUM * G3);
        int r = rem / G3, n = rem - r * G3;
        g_Q[idx]  = (r < 64) ? Wdg[(l*64 + r) * G3 + n] : Wog[(l*32 + (r-64)) * G3 + n];
        g_Qu[idx] = (r < 64) ? Udg[(l*64 + r) * G3 + n] : Uog[(l*32 + (r-64)) * G3 + n];
    }
    if (idx < PN) {
        int l = idx / (NIN * RANKSUM);
        int rem = idx - l * (NIN * RANKSUM);
        int k = rem / RANKSUM, j = rem - k * RANKSUM;
        g_P[idx]  = (j < 64) ? Wd[(l*NIN + k) * 64 + j] : Wo[(l*NIN + k) * 32 + (j-64)];
        g_Pu[idx] = (j < 64) ? Ud[(l*NIN + k) * 64 + j] : Uo[(l*NIN + k) * 32 + (j-64)];
    }
}

// ---------------------------------------------------------------------------
// Generic tiled fp32 GEMM: C[M,N] = A[M,K] @ B[K,N] (+ bias)
// BM=64, BN=64, BK=16, 256 threads, 4x4 microtile. M%64==0, K%16==0, N%4==0.
// ---------------------------------------------------------------------------
__global__ void __launch_bounds__(256)
gemm_tiled(const float* __restrict__ A, const float* __restrict__ B,
           const float* __restrict__ bias, float* __restrict__ C,
           int M, int N, int K)
{
    __shared__ float As[16][64];
    __shared__ float Bs[16][68];

    const int tid = threadIdx.x;
    const int tm = tid >> 4, tn = tid & 15;
    const size_t bm = (size_t)blockIdx.x * 64;
    const int bn = blockIdx.y * 64;

    const int ar = tid >> 2, ak = (tid & 3) << 2;
    const int brow = tid >> 4, bcol = (tid & 15) << 2;

    float acc[4][4];
#pragma unroll
    for (int i = 0; i < 4; ++i)
#pragma unroll
        for (int j = 0; j < 4; ++j) acc[i][j] = 0.f;

    for (int k0 = 0; k0 < K; k0 += 16) {
        float4 av = *(const float4*)(A + (bm + ar) * (size_t)K + k0 + ak);
        As[ak + 0][ar] = av.x; As[ak + 1][ar] = av.y;
        As[ak + 2][ar] = av.z; As[ak + 3][ar] = av.w;

        float4 bv = make_float4(0.f, 0.f, 0.f, 0.f);
        if (bn + bcol < N)
            bv = *(const float4*)(B + (size_t)(k0 + brow) * N + bn + bcol);
        *(float4*)&Bs[brow][bcol] = bv;
        __syncthreads();

#pragma unroll
        for (int k = 0; k < 16; ++k) {
            float4 a = *(const float4*)&As[k][tm << 2];
            float4 b = *(const float4*)&Bs[k][tn << 2];
            acc[0][0] = fmaf(a.x, b.x, acc[0][0]); acc[0][1] = fmaf(a.x, b.y, acc[0][1]);
            acc[0][2] = fmaf(a.x, b.z, acc[0][2]); acc[0][3] = fmaf(a.x, b.w, acc[0][3]);
            acc[1][0] = fmaf(a.y, b.x, acc[1][0]); acc[1][1] = fmaf(a.y, b.y, acc[1][1]);
            acc[1][2] = fmaf(a.y, b.z, acc[1][2]); acc[1][3] = fmaf(a.y, b.w, acc[1][3]);
            acc[2][0] = fmaf(a.z, b.x, acc[2][0]); acc[2][1] = fmaf(a.z, b.y, acc[2][1]);
            acc[2][2] = fmaf(a.z, b.z, acc[2][2]); acc[2][3] = fmaf(a.z, b.w, acc[2][3]);
            acc[3][0] = fmaf(a.w, b.x, acc[3][0]); acc[3][1] = fmaf(a.w, b.y, acc[3][1]);
            acc[3][2] = fmaf(a.w, b.z, acc[3][2]); acc[3][3] = fmaf(a.w, b.w, acc[3][3]);
        }
        __syncthreads();
    }

#pragma unroll
    for (int i = 0; i < 4; ++i) {
        size_t row = bm + (tm << 2) + i;
#pragma unroll
        for (int j = 0; j < 4; ++j) {
            int colj = bn + (tn << 2) + j;
            if (colj < N) {
                float v = acc[i][j];
                if (bias) v += bias[colj];
                C[row * (size_t)N + colj] = v;
            }
        }
    }
}

// ---------------------------------------------------------------------------
// Persistent recurrent kernel, v2.
//
// Cluster of 8 CTAs = one batch group of 16 rows. CTA c owns h-cols
// [32c,32c+32) and the matching z/r/c columns of Ueff (96 KB stationary in
// SMEM, layout [k][gate][32cols]). h exchanged via L2-resident global double
// buffer + cluster barrier.
//
// 256 threads = 8 warps: kq = w>>1 (k-quarter, 64 k each), cg = w&1
// (16-col half). Lane: cp = lane&7 -> col pair (2 cols), rp = lane>>3 ->
// 4 rows. Inner loop uses packed fma.rn.f32x2 over col pairs (u pair is a
// contiguous LDS.64; h is duplicated with one mov.b64). kq!=0 partials are
// reduced through smem; kq==0 warps run the gate epilogue.
// ---------------------------------------------------------------------------
#define RNN_SMEM  (HID*96*4 + HID*16*4 + 3*2*32*12*8)   // 98304+16384+18432=133120

__device__ __forceinline__ float sigmoidf_(float x)
{
    return __fdividef(1.f, 1.f + __expf(-x));
}
__device__ __forceinline__ float tanhf_(float x)
{
    return __fdividef(2.f, 1.f + __expf(-2.f * x)) - 1.f;
}

__global__ void __cluster_dims__(8, 1, 1) __launch_bounds__(256, 1)
rnn_kernel(const float* __restrict__ Ueff,   // [256,768] this layer
           const float* __restrict__ wx,     // [B*T,768]
           float* __restrict__ out_x,        // [B*T,256]
           float* __restrict__ hT_out,       // out + OUT0 + l*256, idx b*512+col
           float* __restrict__ hbuf)         // g_h
{
    extern __shared__ float smem[];
    float* sU  = smem;            // [256][3][32]  24576 floats
    float* sh_ = smem + 24576;    // [256 k][16 rows] 4096 floats
    unsigned long long* red = (unsigned long long*)(smem + 28672); // [3][2][32][12]

    const int c  = blockIdx.x & 7;      // column group (== cluster rank)
    const int g  = blockIdx.x >> 3;     // batch group
    const int tid = threadIdx.x;
    const int w = tid >> 5, lane = tid & 31;
    const int kq = w >> 1;              // k-quarter 0..3
    const int cg = w & 1;               // 16-col half 0..1
    const int cp = lane & 7;            // col pair
    const int rp = lane >> 3;           // row quad
    const int b0 = g << 4;

    // Stationary Ueff slice, interleaved [k][gate][32 cols]
    for (int idx = tid; idx < HID * 96; idx += 256) {
        int k = idx / 96, r = idx - k * 96;
        sU[idx] = Ueff[k * G3 + ((r >> 5) << 8) + (c << 5) + (r & 31)];
    }
    // h0 = 0
    for (int i = tid; i < 1024; i += 256)
        ((float4*)sh_)[i] = make_float4(0.f, 0.f, 0.f, 0.f);
    __syncthreads();

    const int colc0 = (cg << 4) + (cp << 1);   // col in CTA (even)
    const int col0  = (c << 5) + colc0;        // global h col (even)
    const int kbase = kq << 6;

    for (int t = 0; t < SEQ; ++t) {
        // ---- prefetch wx for this step (kq==0 lanes own the outputs) ----
        float2 wxa[3][4];
        if (kq == 0) {
#pragma unroll
            for (int i = 0; i < 4; ++i) {
                const float* p = wx + ((size_t)(b0 + (rp << 2) + i) * SEQ + t) * G3 + col0;
                wxa[0][i] = *(const float2*)(p);
                wxa[1][i] = *(const float2*)(p + 256);
                wxa[2][i] = *(const float2*)(p + 512);
            }
        }

        // ---- partial uh over this warp's k-quarter (packed f32x2) ----
        unsigned long long az[4]  = {0ull, 0ull, 0ull, 0ull};
        unsigned long long arr[4] = {0ull, 0ull, 0ull, 0ull};
        unsigned long long ac[4]  = {0ull, 0ull, 0ull, 0ull};
        {
            const float* hP = sh_ + (kbase << 4) + (rp << 2);
            const float* uP = sU + kbase * 96 + colc0;
#pragma unroll 4
            for (int kk = 0; kk < 64; ++kk) {
                const float4 hq = *(const float4*)hP;
                const unsigned long long uz  = *(const unsigned long long*)(uP);
                const unsigned long long ur_ = *(const unsigned long long*)(uP + 32);
                const unsigned long long uc_ = *(const unsigned long long*)(uP + 64);
                const unsigned long long h0 = dup2(hq.x), h1 = dup2(hq.y);
                const unsigned long long h2 = dup2(hq.z), h3 = dup2(hq.w);
                fma2(az[0], h0, uz);  fma2(arr[0], h0, ur_);  fma2(ac[0], h0, uc_);
                fma2(az[1], h1, uz);  fma2(arr[1], h1, ur_);  fma2(ac[1], h1, uc_);
                fma2(az[2], h2, uz);  fma2(arr[2], h2, ur_);  fma2(ac[2], h2, uc_);
                fma2(az[3], h3, uz);  fma2(arr[3], h3, ur_);  fma2(ac[3], h3, uc_);
                hP += 16; uP += 96;
            }
        }

        // ---- k-split reduction through smem ----
        if (kq != 0) {
            unsigned long long* s = red + (((kq - 1) * 2 + cg) * 32 + lane) * 12;
#pragma unroll
            for (int i = 0; i < 4; ++i) {
                s[i] = az[i]; s[4 + i] = arr[i]; s[8 + i] = ac[i];
            }
        }
        __syncthreads();

        if (kq == 0) {
#pragma unroll
            for (int s3 = 0; s3 < 3; ++s3) {
                const unsigned long long* s = red + ((s3 * 2 + cg) * 32 + lane) * 12;
#pragma unroll
                for (int i = 0; i < 4; ++i) {
                    az[i]  = add2(az[i],  s[i]);
                    arr[i] = add2(arr[i], s[4 + i]);
                    ac[i]  = add2(ac[i],  s[8 + i]);
                }
            }

            // ---- gates + h update (4 rows x 2 cols per lane) ----
            float hc0[4], hc1[4];
#pragma unroll
            for (int i = 0; i < 4; ++i) {
                const int rl = (rp << 2) + i;
                const float2 a2 = unpack2(az[i]);
                const float2 r2 = unpack2(arr[i]);
                const float2 c2 = unpack2(ac[i]);
                const float hp0 = sh_[col0 * 16 + rl];
                const float hp1 = sh_[(col0 + 1) * 16 + rl];
                const float z0 = sigmoidf_(wxa[0][i].x + a2.x);
                const float z1 = sigmoidf_(wxa[0][i].y + a2.y);
                const float r0 = sigmoidf_(wxa[1][i].x + r2.x);
                const float r1 = sigmoidf_(wxa[1][i].y + r2.y);
                const float cc0 = tanhf_(wxa[2][i].x + r0 * c2.x);
                const float cc1 = tanhf_(wxa[2][i].y + r1 * c2.y);
                hc0[i] = z0 * hp0 + (1.f - z0) * cc0;
                hc1[i] = z1 * hp1 + (1.f - z1) * cc1;
                float* op = out_x + ((size_t)(b0 + rl) * SEQ + t) * HID + col0;
                *(float2*)op = make_float2(hc0[i], hc1[i]);
                if (t == SEQ - 1)
                    *(float2*)(hT_out + (size_t)(b0 + rl) * 512 + col0) =
                        make_float2(hc0[i], hc1[i]);
            }

            // publish h_{t+1} slice (2 cols) to the group double buffer
            const int nb = (t + 1) & 1;
            float* hg = hbuf + ((size_t)(nb * 16 + g) * HID + col0) * 16 + (rp << 2);
            *(float4*)hg        = make_float4(hc0[0], hc0[1], hc0[2], hc0[3]);
            *(float4*)(hg + 16) = make_float4(hc1[0], hc1[1], hc1[2], hc1[3]);
        }

        // cluster barrier (writer's arrive releases its global stores)
        asm volatile("barrier.cluster.arrive.aligned;" ::: "memory");
        asm volatile("barrier.cluster.wait.aligned;" ::: "memory");

        // reload full h_{t+1} for this group into SMEM
        const int nb = (t + 1) & 1;
        const float4* src = (const float4*)(hbuf + (size_t)(nb * 16 + g) * HID * 16);
#pragma unroll
        for (int i = tid; i < 1024; i += 256)
            ((float4*)sh_)[i] = src[i];
        __syncthreads();
    }
}

// ---------------------------------------------------------------------------
// Launch
// ---------------------------------------------------------------------------
extern "C" void kernel_launch(void* const* d_in, const int* in_sizes, int n_in,
                              void* d_out, int out_size)
{
    const float* x   = (const float*)d_in[0];
    const float* Wd  = (const float*)d_in[1];
    const float* Wdg = (const float*)d_in[2];
    const float* Wo  = (const float*)d_in[3];
    const float* Wog = (const float*)d_in[4];
    const float* Ud  = (const float*)d_in[5];
    const float* Udg = (const float*)d_in[6];
    const float* Uo  = (const float*)d_in[7];
    const float* Uog = (const float*)d_in[8];
    const float* bb  = (const float*)d_in[9];
    float* out = (float*)d_out;

    float *pT, *pWX, *pX1, *pP, *pQ, *pPu, *pQu, *pUeff, *pH;
    cudaGetSymbolAddress((void**)&pT,   g_t_buf);
    cudaGetSymbolAddress((void**)&pWX,  g_wx_buf);
    cudaGetSymbolAddress((void**)&pX1,  g_x1);
    cudaGetSymbolAddress((void**)&pP,   g_P);
    cudaGetSymbolAddress((void**)&pQ,   g_Q);
    cudaGetSymbolAddress((void**)&pPu,  g_Pu);
    cudaGetSymbolAddress((void**)&pQu,  g_Qu);
    cudaGetSymbolAddress((void**)&pUeff, g_Ueff);
    cudaGetSymbolAddress((void**)&pH,   g_h);

    cudaFuncSetAttribute(rnn_kernel, cudaFuncAttributeMaxDynamicSharedMemorySize, RNN_SMEM);

    // 1. pack low-rank factors
    pack_kernel<<<(LAYERS * RANKSUM * G3 + 255) / 256, 256>>>(Wd, Wdg, Wo, Wog,
                                                              Ud, Udg, Uo, Uog);
    // 2. dense recurrent weights: Ueff[l] = Pu[l] @ Qu[l]  (256x768, K=96)
    for (int l = 0; l < LAYERS; ++l)
        gemm_tiled<<<dim3(HID / 64, G3 / 64), 256>>>(
            pPu + (size_t)l * HID * RANKSUM, pQu + (size_t)l * RANKSUM * G3,
            nullptr, pUeff + (size_t)l * HID * G3, HID, G3, RANKSUM);

    const size_t OUT0 = (size_t)ROWS * HID;   // 33,554,432

    for (int l = 0; l < LAYERS; ++l) {
        const float* xin = (l == 0) ? x : pX1;
        // 3. stage-1: T = x @ [Wd|Wo]   (131072 x 96, K=256)
        gemm_tiled<<<dim3(ROWS / 64, 2), 256>>>(
            xin, pP + (size_t)l * NIN * RANKSUM, nullptr, pT, ROWS, RANKSUM, NIN);
        // 4. stage-2: wx = T @ [Wdg;Wog] + b   (131072 x 768, K=96)
        gemm_tiled<<<dim3(ROWS / 64, G3 / 64), 256>>>(
            pT, pQ + (size_t)l * RANKSUM * G3, bb + l * G3, pWX, ROWS, G3, RANKSUM);
        // 5. sequential scan (persistent cluster kernel)
        float* ox = (l == LAYERS - 1) ? out : pX1;
        rnn_kernel<<<128, 256, RNN_SMEM>>>(
            pUeff + (size_t)l * HID * G3, pWX, ox, out + OUT0 + l * HID, pH);
    }
}